// round 8
// baseline (speedup 1.0000x reference)
#include <cuda_runtime.h>
#include <stdint.h>

#define N_PTS   50000
#define B_ROWS  512
#define E_DIM   16
#define KSEL    20
#define TILE    128          // candidates per tile (1 per group-thread)
#define BTHR    256          // 2 groups x 128 threads
#define G_ROWS  8
#define RPG     4            // rows per group (in registers)
#define SPLITS  2
#define NGRP    (B_ROWS / G_ROWS)      // 64
#define NBLK    (NGRP * 2 * SPLITS)    // 256
#define HID     64
#define FULLM   0xffffffffu

typedef unsigned long long ull;

__device__ float g_feats[B_ROWS][8];
__device__ float g_pval[2][NGRP][SPLITS][G_ROWS][KSEL];
__device__ int   g_pidx[2][NGRP][SPLITS][G_ROWS][KSEL];
__device__ int   g_flag[2][NGRP];
__device__ int   g_done = 0;

static __device__ __forceinline__ float finf() { return __int_as_float(0x7f800000); }

static __device__ __forceinline__ ull pk2(float lo, float hi) {
    ull r; asm("mov.b64 %0,{%1,%2};" : "=l"(r) : "f"(lo), "f"(hi)); return r;
}
static __device__ __forceinline__ void upk2(ull v, float& lo, float& hi) {
    asm("mov.b64 {%0,%1},%2;" : "=f"(lo), "=f"(hi) : "l"(v));
}
static __device__ __forceinline__ ull fma2(ull a, ull b, ull c) {
    ull d; asm("fma.rn.f32x2 %0,%1,%2,%3;" : "=l"(d) : "l"(a), "l"(b), "l"(c)); return d;
}
static __device__ __forceinline__ ull add2(ull a, ull b) {
    ull d; asm("add.rn.f32x2 %0,%1,%2;" : "=l"(d) : "l"(a), "l"(b)); return d;
}

// ---------------------------------------------------------------------------
// grid = (64 groups, 2 sets, 2 splits) = 256 blocks x 256 threads, occ 2/SM.
// Two thread-groups of 128; group g holds q for rows 4g..4g+3 in REGISTERS
// (no smem q-broadcast). Each group computes its 4 rows for the full tile;
// candidate lines are read by both groups (2nd read is an L1 hit).
// Phase B: warp w scans row w (1 LDS.128 + hitmask + redux).
// ---------------------------------------------------------------------------
__global__ __launch_bounds__(BTHR, 2)
void knn_kernel(const float* __restrict__ emb0, const float* __restrict__ emb1,
                const float* __restrict__ rctx0, const float* __restrict__ rctx1,
                const int* __restrict__ idx0, const int* __restrict__ idx1,
                const float* __restrict__ mean_in, const float* __restrict__ std_in,
                const float* __restrict__ W1, const float* __restrict__ b1,
                const float* __restrict__ Wm, const float* __restrict__ bm,
                const float* __restrict__ Ws, const float* __restrict__ bs,
                float* __restrict__ out, int n) {
    const int grp   = blockIdx.x;
    const int set   = blockIdx.y;
    const int split = blockIdx.z;
    const float* __restrict__ emb  = set ? emb1 : emb0;
    const float* __restrict__ rctx = set ? rctx1 : rctx0;
    const int*   __restrict__ idxp = set ? idx1 : idx0;

    const int rowbase = grp * G_ROWS;
    const int tid  = threadIdx.x;
    const int lane = tid & 31;
    const int w    = tid >> 5;          // warp 0..7 == local row in phase B
    const int g    = tid >> 7;          // thread-group 0/1 -> rows 4g..4g+3
    const int lt   = tid & 127;

    __shared__ float sbuf[2][G_ROWS][TILE];   // [buf][row][cand]: 8KB
    __shared__ int   smflag[2];

    // ---- q for this group's 4 rows, packed -2*q, in registers ----
    ull q2[RPG][8];
#pragma unroll
    for (int r = 0; r < RPG; r++) {
        int si = idxp[rowbase + RPG * g + r];
        const float4* qp = reinterpret_cast<const float4*>(emb + (size_t)si * E_DIM);
#pragma unroll
        for (int c = 0; c < 4; c++) {
            float4 v = qp[c];
            q2[r][2 * c + 0] = pk2(-2.f * v.x, -2.f * v.y);
            q2[r][2 * c + 1] = pk2(-2.f * v.z, -2.f * v.w);
        }
    }
    const int selfi = idxp[rowbase + w];   // phase-B row's self index

    const int halfn  = (n + SPLITS - 1) / SPLITS;
    const int jbeg   = split * halfn;
    const int jend   = min(n, jbeg + halfn);
    const int ntiles = (jend - jbeg + TILE - 1) / TILE;

    // ---- top-k state (lanes 0..19 ascending) ----
    float kval   = finf();
    int   kidx   = -1;
    float thresh = finf();

    auto insert = [&](float bv, int bj) {
        float pv = __shfl_up_sync(FULLM, kval, 1);
        int   pj = __shfl_up_sync(FULLM, kidx, 1);
        if (lane < KSEL && bv < kval) {
            if (lane == 0 || bv >= pv) { kval = bv; kidx = bj; }
            else                        { kval = pv; kidx = pj; }
        }
        thresh = __shfl_sync(FULLM, kval, KSEL - 1);
    };

    // ---- Phase B: warp w scans row w: 1 LDS.128 per thread ----
    auto phaseB = [&](int t) {
        const int buf  = t & 1;
        const int base = jbeg + t * TILE;
        float4 f4 = *reinterpret_cast<const float4*>(&sbuf[buf][w][4 * lane]);
        float v[4] = {f4.x, f4.y, f4.z, f4.w};
        unsigned hm = 0;
#pragma unroll
        for (int i = 0; i < 4; i++) {
            int j = base + 4 * lane + i;
            if (v[i] < thresh && j != selfi) hm |= (1u << i);
        }
        unsigned red = __reduce_or_sync(FULLM, hm);
        while (red) {
            int i = __ffs(red) - 1; red &= red - 1;
            unsigned m = __ballot_sync(FULLM, (hm >> i) & 1u);
            float vi = v[i];
            int   ji = base + 4 * lane + i;
            while (m) {
                int src = __ffs(m) - 1; m &= m - 1;
                float bv = __shfl_sync(FULLM, vi, src);
                int   bj = __shfl_sync(FULLM, ji, src);
                if (bv < thresh) insert(bv, bj);
            }
        }
    };

    // ---- main loop: phaseA(t) -> prefetch(t+1) -> bar -> phaseB(t) ----
    ull e[8];
    bool vld = false;
    {   // preload tile 0
        int j = jbeg + lt;
        vld = (j < jend);
        if (vld) {
            const ulonglong2* p = reinterpret_cast<const ulonglong2*>(emb + (size_t)j * E_DIM);
            ulonglong2 a = p[0], b = p[1], c = p[2], d = p[3];
            e[0]=a.x; e[1]=a.y; e[2]=b.x; e[3]=b.y; e[4]=c.x; e[5]=c.y; e[6]=d.x; e[7]=d.y;
        }
    }

    for (int t = 0; t < ntiles; t++) {
        const int buf = t & 1;
        // phase A: norm + 4-row dot products
        ull nA = 0, nB = 0;
#pragma unroll
        for (int c = 0; c < 8; c += 2) {
            nA = fma2(e[c], e[c], nA);
            nB = fma2(e[c + 1], e[c + 1], nB);
        }
        ull nrm = add2(nA, nB);
        ull acc[RPG];
#pragma unroll
        for (int r = 0; r < RPG; r++) acc[r] = nrm;
#pragma unroll
        for (int c = 0; c < 8; c++) {
            ull ec = e[c];
            acc[0] = fma2(q2[0][c], ec, acc[0]);
            acc[1] = fma2(q2[1][c], ec, acc[1]);
            acc[2] = fma2(q2[2][c], ec, acc[2]);
            acc[3] = fma2(q2[3][c], ec, acc[3]);
        }
#pragma unroll
        for (int r = 0; r < RPG; r++) {
            float lo, hi; upk2(acc[r], lo, hi);
            sbuf[buf][RPG * g + r][lt] = vld ? (lo + hi) : finf();
        }
        // prefetch tile t+1 (consumed after the barrier)
        if (t + 1 < ntiles) {
            int j = jbeg + (t + 1) * TILE + lt;
            vld = (j < jend);
            if (vld) {
                const ulonglong2* p = reinterpret_cast<const ulonglong2*>(emb + (size_t)j * E_DIM);
                ulonglong2 a = p[0], b = p[1], c = p[2], d = p[3];
                e[0]=a.x; e[1]=a.y; e[2]=b.x; e[3]=b.y; e[4]=c.x; e[5]=c.y; e[6]=d.x; e[7]=d.y;
            }
        }
        __syncthreads();
        phaseB(t);
    }

    // ---- split rendezvous: per-split partial slots ----
    if (lane < KSEL) {
        g_pval[set][grp][split][w][lane] = kval;
        g_pidx[set][grp][split][w][lane] = kidx;
    }
    __threadfence();
    __syncthreads();
    if (tid == 0) smflag[0] = atomicAdd(&g_flag[set][grp], 1);
    __syncthreads();

    if (smflag[0] == 1) {                 // second arrival merges + features
        __threadfence();
        const int po = 1 - split;
        for (int i = 0; i < KSEL; i++) {
            float bv = g_pval[set][grp][po][w][i];
            int   bj = g_pidx[set][grp][po][w][i];
            if (bv < thresh) insert(bv, bj);
        }
        // |a|^2 for row w from this thread's q2 (row w is local row w&3 of group w>>2)
        ull t0 = 0;
#pragma unroll
        for (int k = 0; k < 8; k++) t0 = fma2(q2[w & 3][k], q2[w & 3][k], t0);
        float lo, hi; upk2(t0, lo, hi);
        float na = 0.25f * (lo + hi);

        const int row = rowbase + w;
        float wgt = 0.f, sel = 0.f;
        if (lane < KSEL) {
            float d2  = fmaxf(kval + na, 0.f);
            float sim = sqrtf(d2) + 0.001f;
            wgt = __expf(-sim);
            sel = rctx[(size_t)row * n + kidx];
        }
        float sw = wgt, ssw = sel * wgt, ss = sel, ss2 = sel * sel;
#pragma unroll
        for (int off = 16; off; off >>= 1) {
            sw  += __shfl_xor_sync(FULLM, sw,  off);
            ssw += __shfl_xor_sync(FULLM, ssw, off);
            ss  += __shfl_xor_sync(FULLM, ss,  off);
            ss2 += __shfl_xor_sync(FULLM, ss2, off);
        }
        if (lane == 0) {
            g_feats[row][0 + set] = sw;
            g_feats[row][2 + set] = ssw / sw;
            float var = (ss2 - ss * ss / (float)KSEL) / (float)(KSEL - 1);
            g_feats[row][4 + set] = sqrtf(fmaxf(var, 0.f));
        }
        if (tid == 0) g_flag[set][grp] = 0;
    }

    // ---- global tail: MLP ----
    __threadfence();
    __syncthreads();
    if (tid == 0) smflag[1] = atomicAdd(&g_done, 1);
    __syncthreads();
    if (smflag[1] != NBLK - 1) return;
    __threadfence();

#pragma unroll
    for (int rr = 0; rr < 2; rr++) {
        int r = tid + BTHR * rr;
        float f[8];
#pragma unroll
        for (int i = 0; i < 6; i++) f[i] = g_feats[r][i];
        f[6] = mean_in[r];
        f[7] = std_in[r];
        float m = bm[0], sd = bs[0];
#pragma unroll 4
        for (int jj = 0; jj < HID; jj++) {
            float h = b1[jj];
#pragma unroll
            for (int i = 0; i < 8; i++) h = fmaf(f[i], W1[i * HID + jj], h);
            h = fmaxf(h, 0.f);
            m  = fmaf(h, Wm[jj], m);
            sd = fmaf(h, Ws[jj], sd);
        }
        out[r]          = m;
        out[B_ROWS + r] = sd;
    }
    if (tid == 0) g_done = 0;
}

// ---------------------------------------------------------------------------
extern "C" void kernel_launch(void* const* d_in, const int* in_sizes, int n_in,
                              void* d_out, int out_size) {
    const float* emb0    = (const float*)d_in[0];
    const float* emb1    = (const float*)d_in[1];
    const float* rctx0   = (const float*)d_in[2];
    const float* rctx1   = (const float*)d_in[3];
    const int*   idx0    = (const int*)  d_in[4];
    const int*   idx1    = (const int*)  d_in[5];
    const float* mean_in = (const float*)d_in[6];
    const float* std_in  = (const float*)d_in[7];
    const float* W1      = (const float*)d_in[8];
    const float* b1      = (const float*)d_in[9];
    const float* Wm      = (const float*)d_in[10];
    const float* bm      = (const float*)d_in[11];
    const float* Ws      = (const float*)d_in[12];
    const float* bs      = (const float*)d_in[13];

    int n = in_sizes[0] / E_DIM;    // 50000

    dim3 grid(NGRP, 2, SPLITS);
    knn_kernel<<<grid, BTHR>>>(emb0, emb1, rctx0, rctx1, idx0, idx1,
                               mean_in, std_in, W1, b1, Wm, bm, Ws, bs,
                               (float*)d_out, n);
}

// round 9
// speedup vs baseline: 1.2138x; 1.2138x over previous
#include <cuda_runtime.h>
#include <stdint.h>

#define N_PTS   50000
#define B_ROWS  512
#define E_DIM   16
#define KSEL    20
#define TILE    128          // candidates per tile (1 per group-thread)
#define BTHR    256          // 2 dim-groups x 128 threads
#define G_ROWS  8
#define SPLITS  2
#define NGRP    (B_ROWS / G_ROWS)      // 64
#define NBLK    (NGRP * 2 * SPLITS)    // 256
#define HID     64
#define FULLM   0xffffffffu
#define BIGV    1.0e37f

typedef unsigned long long ull;

__device__ float g_feats[B_ROWS][8];
__device__ float g_pval[2][NGRP][SPLITS][G_ROWS][KSEL];
__device__ int   g_pidx[2][NGRP][SPLITS][G_ROWS][KSEL];
__device__ int   g_flag[2][NGRP];
__device__ int   g_done = 0;

static __device__ __forceinline__ float finf() { return __int_as_float(0x7f800000); }

static __device__ __forceinline__ ull pk2(float lo, float hi) {
    ull r; asm("mov.b64 %0,{%1,%2};" : "=l"(r) : "f"(lo), "f"(hi)); return r;
}
static __device__ __forceinline__ void upk2(ull v, float& lo, float& hi) {
    asm("mov.b64 {%0,%1},%2;" : "=f"(lo), "=f"(hi) : "l"(v));
}
static __device__ __forceinline__ ull fma2(ull a, ull b, ull c) {
    ull d; asm("fma.rn.f32x2 %0,%1,%2,%3;" : "=l"(d) : "l"(a), "l"(b), "l"(c)); return d;
}
static __device__ __forceinline__ ull add2(ull a, ull b) {
    ull d; asm("add.rn.f32x2 %0,%1,%2;" : "=l"(d) : "l"(a), "l"(b)); return d;
}

// ---------------------------------------------------------------------------
// DIMENSION-SPLIT kernel. grid = (64 groups, 2 sets, 2 splits), block = 256.
// Thread-group g (128 threads) owns dims [8g, 8g+8) of every candidate:
//   - q for ALL 8 rows but only 8 dims -> 64 regs/thread (occupancy-safe)
//   - candidate bytes are read ONCE per SM (groups read complementary halves)
//   - each group writes partial s (half-norm + half-dot) to sbuf[g][row][cand]
// Phase B: warp w = row w: sum the two halves, hitmask + redux, sorted
// warp-distributed top-20 insert. Threshold lives in-warp only.
// ---------------------------------------------------------------------------
__global__ __launch_bounds__(BTHR, 2)
void knn_kernel(const float* __restrict__ emb0, const float* __restrict__ emb1,
                const float* __restrict__ rctx0, const float* __restrict__ rctx1,
                const int* __restrict__ idx0, const int* __restrict__ idx1,
                const float* __restrict__ mean_in, const float* __restrict__ std_in,
                const float* __restrict__ W1, const float* __restrict__ b1,
                const float* __restrict__ Wm, const float* __restrict__ bm,
                const float* __restrict__ Ws, const float* __restrict__ bs,
                float* __restrict__ out, int n) {
    const int grp   = blockIdx.x;
    const int set   = blockIdx.y;
    const int split = blockIdx.z;
    const float* __restrict__ emb  = set ? emb1 : emb0;
    const float* __restrict__ rctx = set ? rctx1 : rctx0;
    const int*   __restrict__ idxp = set ? idx1 : idx0;

    const int rowbase = grp * G_ROWS;
    const int tid  = threadIdx.x;
    const int lane = tid & 31;
    const int w    = tid >> 5;          // warp 0..7 == row owner in phase B
    const int g    = tid >> 7;          // dim-group 0/1 -> dims 8g..8g+7
    const int lt   = tid & 127;         // candidate slot within tile

    __shared__ float sbuf[2][2][G_ROWS][TILE];  // [buf][dimgrp][row][cand] 32KB
    __shared__ float na_sm[G_ROWS];
    __shared__ int   self_sm[G_ROWS];
    __shared__ int   smflag[2];

    // ---- stage self idx + |a|^2 (warp r handles row r) ----
    if (w < G_ROWS) {
        int si = 0;
        if (lane == 0) si = idxp[rowbase + w];
        si = __shfl_sync(FULLM, si, 0);
        if (lane == 0) self_sm[w] = si;
        float nx = 0.f;
        if (lane < 8) {
            float2 v = reinterpret_cast<const float2*>(emb + (size_t)si * E_DIM)[lane];
            nx = v.x * v.x + v.y * v.y;
        }
        nx += __shfl_xor_sync(FULLM, nx, 4);
        nx += __shfl_xor_sync(FULLM, nx, 2);
        nx += __shfl_xor_sync(FULLM, nx, 1);
        if (lane == 0) na_sm[w] = nx;
    }

    // ---- q for all 8 rows, THIS group's 8 dims, packed -2*q: 32 ull ----
    ull q2[G_ROWS][4];
#pragma unroll
    for (int r = 0; r < G_ROWS; r++) {
        int si = idxp[rowbase + r];
        const float4* qp = reinterpret_cast<const float4*>(
            emb + (size_t)si * E_DIM + 8 * g);
        float4 v0 = qp[0], v1 = qp[1];
        q2[r][0] = pk2(-2.f * v0.x, -2.f * v0.y);
        q2[r][1] = pk2(-2.f * v0.z, -2.f * v0.w);
        q2[r][2] = pk2(-2.f * v1.x, -2.f * v1.y);
        q2[r][3] = pk2(-2.f * v1.z, -2.f * v1.w);
    }
    __syncthreads();
    const int selfi = self_sm[w];

    const int halfn  = (n + SPLITS - 1) / SPLITS;
    const int jbeg   = split * halfn;
    const int jend   = min(n, jbeg + halfn);
    const int ntiles = (jend - jbeg + TILE - 1) / TILE;

    // ---- top-k state (lanes 0..19 ascending) ----
    float kval   = finf();
    int   kidx   = -1;
    float thresh = finf();

    auto insert = [&](float bv, int bj) {
        float pv = __shfl_up_sync(FULLM, kval, 1);
        int   pj = __shfl_up_sync(FULLM, kidx, 1);
        if (lane < KSEL && bv < kval) {
            if (lane == 0 || bv >= pv) { kval = bv; kidx = bj; }
            else                        { kval = pv; kidx = pj; }
        }
        thresh = __shfl_sync(FULLM, kval, KSEL - 1);
    };

    // ---- phase B: warp w sums halves of row w, scans 128 cands ----
    auto phaseB = [&](int t) {
        const int buf  = t & 1;
        const int base = jbeg + t * TILE;
        float4 a = reinterpret_cast<const float4*>(&sbuf[buf][0][w][0])[lane];
        float4 b = reinterpret_cast<const float4*>(&sbuf[buf][1][w][0])[lane];
        float v[4] = {a.x + b.x, a.y + b.y, a.z + b.z, a.w + b.w};
        unsigned hm = 0;
#pragma unroll
        for (int i = 0; i < 4; i++) {
            int j = base + 4 * lane + i;
            if (v[i] < thresh && j != selfi) hm |= (1u << i);
        }
        unsigned red = __reduce_or_sync(FULLM, hm);
        while (red) {
            int i = __ffs(red) - 1; red &= red - 1;
            unsigned m = __ballot_sync(FULLM, (hm >> i) & 1u);
            float vi = v[i];
            int   ji = base + 4 * lane + i;
            while (m) {
                int src = __ffs(m) - 1; m &= m - 1;
                float bv = __shfl_sync(FULLM, vi, src);
                int   bj = __shfl_sync(FULLM, ji, src);
                if (bv < thresh) insert(bv, bj);
            }
        }
    };

    // ---- main loop ----
    ull e[4];                            // this group's 32B of the candidate
    bool vld;
    {
        int j = jbeg + lt;
        vld = (j < jend);
        if (vld) {
            const ulonglong2* p = reinterpret_cast<const ulonglong2*>(
                emb + (size_t)j * E_DIM + 8 * g);
            ulonglong2 x = p[0], y = p[1];
            e[0] = x.x; e[1] = x.y; e[2] = y.x; e[3] = y.y;
        }
    }

    for (int t = 0; t < ntiles; t++) {
        const int buf = t & 1;
        // partial s = half-norm + half-dot for all 8 rows
        ull nA = fma2(e[0], e[0], 0), nB = fma2(e[1], e[1], 0);
        nA = fma2(e[2], e[2], nA);     nB = fma2(e[3], e[3], nB);
        ull nrm = add2(nA, nB);
        ull acc[G_ROWS];
#pragma unroll
        for (int r = 0; r < G_ROWS; r++) acc[r] = nrm;
#pragma unroll
        for (int k = 0; k < 4; k++) {
            ull ek = e[k];
#pragma unroll
            for (int r = 0; r < G_ROWS; r++)
                acc[r] = fma2(q2[r][k], ek, acc[r]);
        }
#pragma unroll
        for (int r = 0; r < G_ROWS; r++) {
            float lo, hi; upk2(acc[r], lo, hi);
            sbuf[buf][g][r][lt] = vld ? (lo + hi) : BIGV;
        }
        // prefetch next tile (covered by barrier + phaseB)
        if (t + 1 < ntiles) {
            int j = jbeg + (t + 1) * TILE + lt;
            vld = (j < jend);
            if (vld) {
                const ulonglong2* p = reinterpret_cast<const ulonglong2*>(
                    emb + (size_t)j * E_DIM + 8 * g);
                ulonglong2 x = p[0], y = p[1];
                e[0] = x.x; e[1] = x.y; e[2] = y.x; e[3] = y.y;
            }
        }
        __syncthreads();
        phaseB(t);
    }

    // ---- split rendezvous ----
    if (lane < KSEL) {
        g_pval[set][grp][split][w][lane] = kval;
        g_pidx[set][grp][split][w][lane] = kidx;
    }
    __threadfence();
    __syncthreads();
    if (tid == 0) smflag[0] = atomicAdd(&g_flag[set][grp], 1);
    __syncthreads();

    if (smflag[0] == 1) {               // second arrival merges + features
        __threadfence();
        const int po = 1 - split;
        for (int i = 0; i < KSEL; i++) {
            float bv = g_pval[set][grp][po][w][i];
            int   bj = g_pidx[set][grp][po][w][i];
            if (bv < thresh) insert(bv, bj);
        }
        const int row = rowbase + w;
        const float na = na_sm[w];
        float wgt = 0.f, sel = 0.f;
        if (lane < KSEL) {
            float d2  = fmaxf(kval + na, 0.f);
            float sim = sqrtf(d2) + 0.001f;
            wgt = __expf(-sim);
            sel = rctx[(size_t)row * n + kidx];
        }
        float sw = wgt, ssw = sel * wgt, ss = sel, ss2 = sel * sel;
#pragma unroll
        for (int off = 16; off; off >>= 1) {
            sw  += __shfl_xor_sync(FULLM, sw,  off);
            ssw += __shfl_xor_sync(FULLM, ssw, off);
            ss  += __shfl_xor_sync(FULLM, ss,  off);
            ss2 += __shfl_xor_sync(FULLM, ss2, off);
        }
        if (lane == 0) {
            g_feats[row][0 + set] = sw;
            g_feats[row][2 + set] = ssw / sw;
            float var = (ss2 - ss * ss / (float)KSEL) / (float)(KSEL - 1);
            g_feats[row][4 + set] = sqrtf(fmaxf(var, 0.f));
        }
        if (tid == 0) g_flag[set][grp] = 0;
    }

    // ---- global tail: MLP ----
    __threadfence();
    __syncthreads();
    if (tid == 0) smflag[1] = atomicAdd(&g_done, 1);
    __syncthreads();
    if (smflag[1] != NBLK - 1) return;
    __threadfence();

#pragma unroll
    for (int rr = 0; rr < 2; rr++) {
        int r = tid + BTHR * rr;
        float f[8];
#pragma unroll
        for (int i = 0; i < 6; i++) f[i] = g_feats[r][i];
        f[6] = mean_in[r];
        f[7] = std_in[r];
        float m = bm[0], sd = bs[0];
#pragma unroll 4
        for (int jj = 0; jj < HID; jj++) {
            float h = b1[jj];
#pragma unroll
            for (int i = 0; i < 8; i++) h = fmaf(f[i], W1[i * HID + jj], h);
            h = fmaxf(h, 0.f);
            m  = fmaf(h, Wm[jj], m);
            sd = fmaf(h, Ws[jj], sd);
        }
        out[r]          = m;
        out[B_ROWS + r] = sd;
    }
    if (tid == 0) g_done = 0;
}

// ---------------------------------------------------------------------------
extern "C" void kernel_launch(void* const* d_in, const int* in_sizes, int n_in,
                              void* d_out, int out_size) {
    const float* emb0    = (const float*)d_in[0];
    const float* emb1    = (const float*)d_in[1];
    const float* rctx0   = (const float*)d_in[2];
    const float* rctx1   = (const float*)d_in[3];
    const int*   idx0    = (const int*)  d_in[4];
    const int*   idx1    = (const int*)  d_in[5];
    const float* mean_in = (const float*)d_in[6];
    const float* std_in  = (const float*)d_in[7];
    const float* W1      = (const float*)d_in[8];
    const float* b1      = (const float*)d_in[9];
    const float* Wm      = (const float*)d_in[10];
    const float* bm      = (const float*)d_in[11];
    const float* Ws      = (const float*)d_in[12];
    const float* bs      = (const float*)d_in[13];

    int n = in_sizes[0] / E_DIM;    // 50000

    dim3 grid(NGRP, 2, SPLITS);
    knn_kernel<<<grid, BTHR>>>(emb0, emb1, rctx0, rctx1, idx0, idx1,
                               mean_in, std_in, W1, b1, Wm, bm, Ws, bs,
                               (float*)d_out, n);
}